// round 4
// baseline (speedup 1.0000x reference)
#include <cuda_runtime.h>
#include <cuda_bf16.h>
#include <cstdint>

// Problem: x [16, 256, 128, 128] f32.
//  1) weight[b,c] = mean over H,W
//  2) idx[b,:] = argsort(weight[b]) ascending, take first 16 (stable)
//  3) out[b,k,:,:] = x[b, idx[b,k], :, :]
//
// R4: persistent fused kernel (R3) with two fixes:
//  - __launch_bounds__(256, 8): cap regs at 32 so every block keeps the
//    R1 mean kernel's 8-blocks/SM occupancy (R3 lost BW to 40 regs -> 6/SM).
//  - gather spread over 64 blocks/batch (quarter planes) so gather blocks
//    finish with their peers and the last-batch tail is <1us.

#define B 16
#define C 256
#define HW 16384          // 128*128
#define K 16

__device__ float g_weight[B * C];
__device__ int   g_count[B];          // reset to 0 by memsetAsync each launch

__global__ __launch_bounds__(256, 8) void fused_kernel(const float* __restrict__ x,
                                                       float* __restrict__ out) {
    const int bc = blockIdx.x;                        // 0..4095
    const int b  = bc >> 8;
    const int t  = threadIdx.x;

    // ---- Phase 1: mean of plane bc (DRAM-bound, 64KB/block) ----
    {
        const float4* __restrict__ p =
            reinterpret_cast<const float4*>(x + (size_t)bc * HW);
        float s0 = 0.f, s1 = 0.f, s2 = 0.f, s3 = 0.f;
#pragma unroll
        for (int i = 0; i < 16; i += 4) {
            float4 v0 = __ldg(&p[t + (i + 0) * 256]);
            float4 v1 = __ldg(&p[t + (i + 1) * 256]);
            float4 v2 = __ldg(&p[t + (i + 2) * 256]);
            float4 v3 = __ldg(&p[t + (i + 3) * 256]);
            s0 += (v0.x + v0.y) + (v0.z + v0.w);
            s1 += (v1.x + v1.y) + (v1.z + v1.w);
            s2 += (v2.x + v2.y) + (v2.z + v2.w);
            s3 += (v3.x + v3.y) + (v3.z + v3.w);
        }
        float s = (s0 + s1) + (s2 + s3);
#pragma unroll
        for (int off = 16; off > 0; off >>= 1)
            s += __shfl_down_sync(0xFFFFFFFFu, s, off);

        __shared__ float sred[8];
        if ((t & 31) == 0) sred[t >> 5] = s;
        __syncthreads();
        if (t < 8) {
            float v = sred[t];
#pragma unroll
            for (int off = 4; off > 0; off >>= 1)
                v += __shfl_down_sync(0xFFu, v, off);
            if (t == 0) {
                g_weight[bc] = v * (1.0f / (float)HW);
                __threadfence();
                atomicAdd(&g_count[b], 1);
            }
        }
    }

    // ---- Phase 2: last 64 blocks of each batch own one quarter-plane ----
    const int r = bc & 255;
    if (r < 192) return;
    const int kk = r - 192;                           // 0..63
    const int k  = kk >> 2;                           // output channel rank
    const int q  = kk & 3;                            // quarter within plane

    if (t == 0) {
        while (atomicAdd(&g_count[b], 0) < C) __nanosleep(128);
    }
    __syncthreads();                                  // all threads see handoff

    __shared__ float sw[C];
    __shared__ int sel;
    sw[t] = __ldcg(&g_weight[b * C + t]);             // L2-coherent read
    __syncthreads();

    const float v = sw[t];
    int rank = 0;
#pragma unroll 8
    for (int j = 0; j < C; ++j) {
        const float u = sw[j];
        rank += (u < v) || (u == v && j < t);
    }
    if (rank == k) sel = t;                           // exactly one thread hits
    __syncthreads();
    const int c = sel;

    const float4* __restrict__ src = reinterpret_cast<const float4*>(
        x + ((size_t)b * C + c) * HW) + q * 1024;
    float4* __restrict__ dst = reinterpret_cast<float4*>(
        out + (size_t)(b * K + k) * HW) + q * 1024;

#pragma unroll
    for (int i = 0; i < 4; ++i) {
        float4 w = __ldg(&src[t + i * 256]);
        __stcs(&dst[t + i * 256], w);                 // streaming store
    }
}

// ---------------------------------------------------------------------------
extern "C" void kernel_launch(void* const* d_in, const int* in_sizes, int n_in,
                              void* d_out, int out_size) {
    const float* x = (const float*)d_in[0];
    float* out = (float*)d_out;

    void* cptr = nullptr;
    cudaGetSymbolAddress(&cptr, g_count);
    cudaMemsetAsync(cptr, 0, B * sizeof(int));        // graph-capturable node

    fused_kernel<<<B * C, 256>>>(x, out);
}

// round 5
// speedup vs baseline: 1.2914x; 1.2914x over previous
#include <cuda_runtime.h>
#include <cuda_bf16.h>
#include <cstdint>

// Problem: x [16, 256, 128, 128] f32.
//  1) weight[b,c] = mean over H,W
//  2) idx[b,:] = argsort(weight[b]) ascending, take first 16 (stable)
//  3) out[b,k,:,:] = x[b, idx[b,k], :, :]
//
// R5: two launches.
//  - mean_select_kernel: R1's 80%-of-peak mean kernel; additionally the
//    LAST block of each batch to finish (atomicAdd ticket == 255, no spin)
//    computes the stable bottom-16 ranks and writes g_idx. 16 blocks chip-
//    wide pay the rank cost; the hot path gains only one atomic per block.
//  - gather_kernel: plain float4 copy of the 16 selected planes per batch.

#define B 16
#define C 256
#define HW 16384          // 128*128
#define HW4 4096          // float4 per plane
#define K 16

__device__ float g_weight[B * C];
__device__ int   g_idx[B * K];
__device__ int   g_count[B];          // reset to 0 by memsetAsync each launch

// ---------------------------------------------------------------------------
__global__ __launch_bounds__(256, 8) void mean_select_kernel(
    const float* __restrict__ x) {
    const int bc = blockIdx.x;                        // 0..4095
    const int b  = bc >> 8;
    const int t  = threadIdx.x;

    // ---- mean of plane bc (DRAM-bound, 64KB/block) ----
    const float4* __restrict__ p =
        reinterpret_cast<const float4*>(x + (size_t)bc * HW);
    float s0 = 0.f, s1 = 0.f, s2 = 0.f, s3 = 0.f;
#pragma unroll
    for (int i = 0; i < 16; i += 4) {
        float4 v0 = __ldg(&p[t + (i + 0) * 256]);
        float4 v1 = __ldg(&p[t + (i + 1) * 256]);
        float4 v2 = __ldg(&p[t + (i + 2) * 256]);
        float4 v3 = __ldg(&p[t + (i + 3) * 256]);
        s0 += (v0.x + v0.y) + (v0.z + v0.w);
        s1 += (v1.x + v1.y) + (v1.z + v1.w);
        s2 += (v2.x + v2.y) + (v2.z + v2.w);
        s3 += (v3.x + v3.y) + (v3.z + v3.w);
    }
    float s = (s0 + s1) + (s2 + s3);
#pragma unroll
    for (int off = 16; off > 0; off >>= 1)
        s += __shfl_down_sync(0xFFFFFFFFu, s, off);

    __shared__ float sred[8];
    __shared__ int   s_last;                          // 1 iff we are batch's last block
    if ((t & 31) == 0) sred[t >> 5] = s;
    __syncthreads();
    if (t < 8) {
        float v = sred[t];
#pragma unroll
        for (int off = 4; off > 0; off >>= 1)
            v += __shfl_down_sync(0xFFu, v, off);
        if (t == 0) {
            g_weight[bc] = v * (1.0f / (float)HW);
            __threadfence();                          // publish mean
            const int old = atomicAdd(&g_count[b], 1);
            s_last = (old == C - 1);                  // last finisher, no spin
        }
    }
    __syncthreads();
    if (!s_last) return;

    // ---- this block is the last of batch b: stable bottom-16 select ----
    __threadfence();                                  // order reads after atomic
    __shared__ float sw[C];
    sw[t] = __ldcg(&g_weight[b * C + t]);
    __syncthreads();

    const float v = sw[t];
    int rank = 0;
#pragma unroll 8
    for (int j = 0; j < C; ++j) {
        const float u = sw[j];
        rank += (u < v) || (u == v && j < t);
    }
    if (rank < K) g_idx[b * K + rank] = t;
}

// ---------------------------------------------------------------------------
// Gather: blockIdx.x = output plane (b*16+k), blockIdx.y = quarter.
// 4 float4 per thread, streaming stores.
// ---------------------------------------------------------------------------
__global__ __launch_bounds__(256) void gather_kernel(const float* __restrict__ x,
                                                     float* __restrict__ out) {
    const int plane = blockIdx.x;                     // 0..255
    const int b = plane >> 4;
    const int c = g_idx[plane];
    const int t = threadIdx.x;

    const float4* __restrict__ src = reinterpret_cast<const float4*>(
        x + ((size_t)b * C + c) * HW) + blockIdx.y * 1024;
    float4* __restrict__ dst = reinterpret_cast<float4*>(
        out + (size_t)plane * HW) + blockIdx.y * 1024;

#pragma unroll
    for (int i = 0; i < 4; ++i) {
        float4 w = __ldg(&src[t + i * 256]);
        __stcs(&dst[t + i * 256], w);
    }
}

// ---------------------------------------------------------------------------
extern "C" void kernel_launch(void* const* d_in, const int* in_sizes, int n_in,
                              void* d_out, int out_size) {
    const float* x = (const float*)d_in[0];
    float* out = (float*)d_out;

    void* cptr = nullptr;
    cudaGetSymbolAddress(&cptr, g_count);
    cudaMemsetAsync(cptr, 0, B * sizeof(int));        // graph-capturable node

    mean_select_kernel<<<B * C, 256>>>(x);
    gather_kernel<<<dim3(B * K, 4), 256>>>(x, out);
}

// round 6
// speedup vs baseline: 1.3088x; 1.0135x over previous
#include <cuda_runtime.h>
#include <cuda_bf16.h>
#include <cstdint>

// Problem: x [16, 256, 128, 128] f32.
//  1) weight[b,c] = mean over H,W
//  2) idx[b,:] = argsort(weight[b]) ascending, take first 16 (stable)
//  3) out[b,k,:,:] = x[b, idx[b,k], :, :]
//
// R6: two launches, no memset node.
//  - mean_select_kernel: 80%-of-peak mean; last finisher per batch (atomic
//    ticket == 255) computes stable bottom-16 and RESETS the counter, so no
//    memset graph node is needed across replays.
//  - gather_kernel: 512 blocks, 8 float4/thread, all loads before stores
//    (MLP=8) to fix the latency-bound 25%-DRAM gather of R5.

#define B 16
#define C 256
#define HW 16384          // 128*128
#define K 16

__device__ float g_weight[B * C];
__device__ int   g_idx[B * K];
__device__ int   g_count[B];          // zero-init; self-reset by last finisher

// ---------------------------------------------------------------------------
__global__ __launch_bounds__(256, 8) void mean_select_kernel(
    const float* __restrict__ x) {
    const int bc = blockIdx.x;                        // 0..4095
    const int b  = bc >> 8;
    const int t  = threadIdx.x;

    // ---- mean of plane bc (DRAM-bound, 64KB/block) ----
    const float4* __restrict__ p =
        reinterpret_cast<const float4*>(x + (size_t)bc * HW);
    float s0 = 0.f, s1 = 0.f, s2 = 0.f, s3 = 0.f;
#pragma unroll
    for (int i = 0; i < 16; i += 4) {
        float4 v0 = __ldg(&p[t + (i + 0) * 256]);
        float4 v1 = __ldg(&p[t + (i + 1) * 256]);
        float4 v2 = __ldg(&p[t + (i + 2) * 256]);
        float4 v3 = __ldg(&p[t + (i + 3) * 256]);
        s0 += (v0.x + v0.y) + (v0.z + v0.w);
        s1 += (v1.x + v1.y) + (v1.z + v1.w);
        s2 += (v2.x + v2.y) + (v2.z + v2.w);
        s3 += (v3.x + v3.y) + (v3.z + v3.w);
    }
    float s = (s0 + s1) + (s2 + s3);
#pragma unroll
    for (int off = 16; off > 0; off >>= 1)
        s += __shfl_down_sync(0xFFFFFFFFu, s, off);

    __shared__ float sred[8];
    __shared__ int   s_last;                          // 1 iff batch's last block
    if ((t & 31) == 0) sred[t >> 5] = s;
    __syncthreads();
    if (t < 8) {
        float v = sred[t];
#pragma unroll
        for (int off = 4; off > 0; off >>= 1)
            v += __shfl_down_sync(0xFFu, v, off);
        if (t == 0) {
            g_weight[bc] = v * (1.0f / (float)HW);
            __threadfence();                          // publish mean
            const int old = atomicAdd(&g_count[b], 1);
            s_last = (old == C - 1);                  // last finisher, no spin
        }
    }
    __syncthreads();
    if (!s_last) return;

    // ---- last block of batch b: stable bottom-16 select + counter reset ----
    __threadfence();                                  // order reads after atomic
    __shared__ float sw[C];
    sw[t] = __ldcg(&g_weight[b * C + t]);
    __syncthreads();

    const float v = sw[t];
    int rank = 0;
#pragma unroll 8
    for (int j = 0; j < C; ++j) {
        const float u = sw[j];
        rank += (u < v) || (u == v && j < t);
    }
    if (rank < K) g_idx[b * K + rank] = t;
    if (t == 0) atomicExch(&g_count[b], 0);           // self-reset for replay
}

// ---------------------------------------------------------------------------
// Gather: blockIdx.x = output plane (b*16+k), blockIdx.y = half-plane.
// 8 float4 per thread, ALL loads issued before any store (MLP=8).
// ---------------------------------------------------------------------------
__global__ __launch_bounds__(256) void gather_kernel(const float* __restrict__ x,
                                                     float* __restrict__ out) {
    const int plane = blockIdx.x;                     // 0..255
    const int b = plane >> 4;
    const int c = __ldcg(&g_idx[plane]);
    const int t = threadIdx.x;

    const float4* __restrict__ src = reinterpret_cast<const float4*>(
        x + ((size_t)b * C + c) * HW) + blockIdx.y * 2048;
    float4* __restrict__ dst = reinterpret_cast<float4*>(
        out + (size_t)plane * HW) + blockIdx.y * 2048;

    float4 w[8];
#pragma unroll
    for (int i = 0; i < 8; ++i)
        w[i] = __ldg(&src[t + i * 256]);              // 8 loads in flight
#pragma unroll
    for (int i = 0; i < 8; ++i)
        __stcs(&dst[t + i * 256], w[i]);              // streaming stores
}

// ---------------------------------------------------------------------------
extern "C" void kernel_launch(void* const* d_in, const int* in_sizes, int n_in,
                              void* d_out, int out_size) {
    const float* x = (const float*)d_in[0];
    float* out = (float*)d_out;

    mean_select_kernel<<<B * C, 256>>>(x);
    gather_kernel<<<dim3(B * K, 2), 256>>>(x, out);
}